// round 3
// baseline (speedup 1.0000x reference)
#include <cuda_runtime.h>
#include <cuda_bf16.h>
#include <cstdint>

// ============================================================================
// Problem constants
// ============================================================================
#define BDIM   32768
#define DDIM   1024

// ============================================================================
// Scratch (device globals — no runtime allocation allowed)
// ============================================================================
__device__ float g_S0t[DDIM * DDIM];
__device__ float g_S1 [DDIM * DDIM];
__device__ float g_S2 [DDIM * DDIM];
__device__ float g_S3 [DDIM * DDIM];
__device__ float g_T0 [DDIM * DDIM];
__device__ float g_T1 [DDIM * DDIM];
__device__ float g_M  [DDIM * DDIM];

// ============================================================================
// Warp MMA helpers (sm_80+ ISA only — NO tcgen05/TMA; ptxas targets plain sm_100)
// ============================================================================
__device__ __forceinline__ uint32_t smem_u32(const void* p) {
    uint32_t a;
    asm("{ .reg .u64 t; cvta.to.shared.u64 t, %1; cvt.u32.u64 %0, t; }"
        : "=r"(a) : "l"(p));
    return a;
}

__device__ __forceinline__ void ldmatrix_x4(uint32_t& r0, uint32_t& r1,
                                            uint32_t& r2, uint32_t& r3,
                                            uint32_t addr) {
    asm volatile("ldmatrix.sync.aligned.m8n8.x4.shared.b16 {%0,%1,%2,%3}, [%4];"
                 : "=r"(r0), "=r"(r1), "=r"(r2), "=r"(r3) : "r"(addr));
}

__device__ __forceinline__ void mma_bf16(float* c, uint32_t a0, uint32_t a1,
                                         uint32_t a2, uint32_t a3,
                                         uint32_t b0, uint32_t b1) {
    asm volatile(
        "mma.sync.aligned.m16n8k16.row.col.f32.bf16.bf16.f32 "
        "{%0,%1,%2,%3}, {%4,%5,%6,%7}, {%8,%9}, {%0,%1,%2,%3};"
        : "+f"(c[0]), "+f"(c[1]), "+f"(c[2]), "+f"(c[3])
        : "r"(a0), "r"(a1), "r"(a2), "r"(a3), "r"(b0), "r"(b1));
}

// ============================================================================
// Softmax over rows of a 1024x1024 matrix; optional transposed write.
// ============================================================================
__global__ void softmax_kernel(const float* __restrict__ P, float* __restrict__ S,
                               int transpose) {
    int row = blockIdx.x;
    const float* p = P + (size_t)row * DDIM;
    int tid = threadIdx.x;  // 256
    __shared__ float red[8];

    float v[4];
    float mx = -3.4e38f;
#pragma unroll
    for (int j = 0; j < 4; j++) { v[j] = p[tid + j * 256]; mx = fmaxf(mx, v[j]); }
#pragma unroll
    for (int o = 16; o; o >>= 1) mx = fmaxf(mx, __shfl_xor_sync(0xffffffffu, mx, o));
    if ((tid & 31) == 0) red[tid >> 5] = mx;
    __syncthreads();
    mx = red[0];
#pragma unroll
    for (int i = 1; i < 8; i++) mx = fmaxf(mx, red[i]);
    __syncthreads();

    float sum = 0.f;
#pragma unroll
    for (int j = 0; j < 4; j++) { v[j] = expf(v[j] - mx); sum += v[j]; }
#pragma unroll
    for (int o = 16; o; o >>= 1) sum += __shfl_xor_sync(0xffffffffu, sum, o);
    if ((tid & 31) == 0) red[tid >> 5] = sum;
    __syncthreads();
    sum = 0.f;
#pragma unroll
    for (int i = 0; i < 8; i++) sum += red[i];
    float inv = 1.0f / sum;

#pragma unroll
    for (int j = 0; j < 4; j++) {
        int c = tid + j * 256;
        float val = v[j] * inv;
        if (transpose) S[(size_t)c * DDIM + row] = val;
        else           S[(size_t)row * DDIM + c] = val;
    }
}

// ============================================================================
// H[d][n*32+o] = sum_i G[d][n*32+i] * Kb[n][i][o]   (right-mul by blockdiag)
// ============================================================================
__global__ void blockdiag_right(const float* __restrict__ G,
                                const float* __restrict__ Kb,
                                float* __restrict__ H) {
    __shared__ float Ks[32][33];
    int n  = blockIdx.x;
    int d0 = blockIdx.y * 8;
    int t  = threadIdx.y * 32 + threadIdx.x;
    for (int idx = t; idx < 1024; idx += 256)
        Ks[idx >> 5][idx & 31] = Kb[n * 1024 + idx];
    __syncthreads();

    int o = threadIdx.x;
    int d = d0 + threadIdx.y;
    const float* g = G + (size_t)d * DDIM + n * 32;
    float s = 0.f;
#pragma unroll
    for (int i = 0; i < 32; i++) s += g[i] * Ks[i][o];
    H[(size_t)d * DDIM + n * 32 + o] = s;
}

// ============================================================================
// TN GEMM: C[m][n] = sum_k A[m][k]*B[n][k]  (+ optional bias[n])
// fp32 in/out. bf16 hi/lo split, 3 MMA passes (Ah*Bh + Ah*Bl + Al*Bh), fp32 acc.
// BM=BN=128, BK=32; 8 warps (2x4), each warp 64x32; mma.sync m16n8k16.
// ============================================================================
#define BK 32
#define PAD 40                         // bf16 elems per smem row (80B: bank-safe)
#define CH_ELEMS (128 * PAD)           // one channel (Ah|Al|Bh|Bl) per stage
#define STAGE_ELEMS (4 * CH_ELEMS)
#define GEMM_SMEM (2 * STAGE_ELEMS * 2) // bytes (bf16)

__global__ void __launch_bounds__(256, 1)
gemm_tn(const float* __restrict__ A, const float* __restrict__ B,
        float* __restrict__ C, int M, int N, int K,
        const float* __restrict__ bias) {
    extern __shared__ __nv_bfloat16 sm[];
    int tid  = threadIdx.x;
    int wid  = tid >> 5;
    int lane = tid & 31;
    int m0 = blockIdx.y * 128;
    int n0 = blockIdx.x * 128;
    int wm = (wid & 1) * 64;   // warp row offset in tile
    int wn = (wid >> 1) * 32;  // warp col offset in tile

    const float* Ag = A + (size_t)m0 * K;
    const float* Bg = B + (size_t)n0 * K;

    float acc[4][4][4];
#pragma unroll
    for (int i = 0; i < 4; i++)
#pragma unroll
        for (int j = 0; j < 4; j++)
#pragma unroll
            for (int q = 0; q < 4; q++) acc[i][j][q] = 0.f;

    // per-thread global-load mapping: 4 float4 per operand per stage
    int lrow[4], lc4[4];
#pragma unroll
    for (int j = 0; j < 4; j++) {
        int f = tid + j * 256;          // 0..1023 float4 slots (128 rows x 8)
        lrow[j] = f >> 3;
        lc4[j]  = f & 7;
    }

    float4 regA[4], regB[4];

    auto issue_loads = [&](int k0) {
#pragma unroll
        for (int j = 0; j < 4; j++) {
            regA[j] = *reinterpret_cast<const float4*>(
                Ag + (size_t)lrow[j] * K + k0 + lc4[j] * 4);
            regB[j] = *reinterpret_cast<const float4*>(
                Bg + (size_t)lrow[j] * K + k0 + lc4[j] * 4);
        }
    };

    auto store_stage = [&](int st) {
        __nv_bfloat16* sAh = sm + st * STAGE_ELEMS;
        __nv_bfloat16* sAl = sAh + CH_ELEMS;
        __nv_bfloat16* sBh = sAl + CH_ELEMS;
        __nv_bfloat16* sBl = sBh + CH_ELEMS;
#pragma unroll
        for (int j = 0; j < 4; j++) {
            int off = lrow[j] * PAD + lc4[j] * 4;
            float va[4] = {regA[j].x, regA[j].y, regA[j].z, regA[j].w};
            float vb[4] = {regB[j].x, regB[j].y, regB[j].z, regB[j].w};
            __nv_bfloat16 ah[4], al[4], bh[4], bl[4];
#pragma unroll
            for (int q = 0; q < 4; q++) {
                ah[q] = __float2bfloat16(va[q]);
                al[q] = __float2bfloat16(va[q] - __bfloat162float(ah[q]));
                bh[q] = __float2bfloat16(vb[q]);
                bl[q] = __float2bfloat16(vb[q] - __bfloat162float(bh[q]));
            }
            *reinterpret_cast<uint2*>(sAh + off) = *reinterpret_cast<uint2*>(ah);
            *reinterpret_cast<uint2*>(sAl + off) = *reinterpret_cast<uint2*>(al);
            *reinterpret_cast<uint2*>(sBh + off) = *reinterpret_cast<uint2*>(bh);
            *reinterpret_cast<uint2*>(sBl + off) = *reinterpret_cast<uint2*>(bl);
        }
    };

    // ldmatrix address offsets (elements) within a channel
    // A (x4, 16x16): row = wm + mi*16 + lane%16, col = kk + (lane/16)*8
    int a_row = wm + (lane & 15);
    int a_col8 = (lane >> 4) * 8;
    // B (x4 covers 2 n-tiles): row = wn + p*16 + lane%8 + ((lane>>3)&1)*8
    int b_row = wn + (lane & 7) + ((lane >> 3) & 1) * 8;
    int b_col8 = (lane >> 4) * 8;

    uint32_t smem_base = smem_u32(sm);

    // prologue
    issue_loads(0);
    store_stage(0);
    __syncthreads();

    int nck = K / BK;
    for (int ck = 0; ck < nck; ck++) {
        if (ck + 1 < nck) issue_loads((ck + 1) * BK);

        int st = ck & 1;
        uint32_t chA = smem_base + (st * STAGE_ELEMS) * 2;
        uint32_t chAl = chA + CH_ELEMS * 2;
        uint32_t chB = chAl + CH_ELEMS * 2;
        uint32_t chBl = chB + CH_ELEMS * 2;

#pragma unroll
        for (int kk = 0; kk < BK; kk += 16) {
            // B fragments: 2 x ldmatrix.x4 per channel (pairs of n-tiles)
            uint32_t bh[2][4], bl[2][4];
#pragma unroll
            for (int p = 0; p < 2; p++) {
                uint32_t off = ((b_row + p * 16) * PAD + kk + b_col8) * 2;
                ldmatrix_x4(bh[p][0], bh[p][1], bh[p][2], bh[p][3], chB + off);
                ldmatrix_x4(bl[p][0], bl[p][1], bl[p][2], bl[p][3], chBl + off);
            }
#pragma unroll
            for (int mi = 0; mi < 4; mi++) {
                uint32_t offA = ((a_row + mi * 16) * PAD + kk + a_col8) * 2;
                uint32_t ah0, ah1, ah2, ah3, al0, al1, al2, al3;
                ldmatrix_x4(ah0, ah1, ah2, ah3, chA + offA);
                ldmatrix_x4(al0, al1, al2, al3, chAl + offA);
#pragma unroll
                for (int ni = 0; ni < 4; ni++) {
                    int p = ni >> 1, s = ni & 1;
                    // x4 regs: {t0.b0, t1.b0, t0.b1, t1.b1}
                    uint32_t b0h = bh[p][s], b1h = bh[p][2 + s];
                    uint32_t b0l = bl[p][s], b1l = bl[p][2 + s];
                    mma_bf16(acc[mi][ni], ah0, ah1, ah2, ah3, b0h, b1h);
                    mma_bf16(acc[mi][ni], ah0, ah1, ah2, ah3, b0l, b1l);
                    mma_bf16(acc[mi][ni], al0, al1, al2, al3, b0h, b1h);
                }
            }
        }

        if (ck + 1 < nck) store_stage((ck + 1) & 1);
        __syncthreads();
    }

    // epilogue: fragment layout m16n8: c0,c1 row=lane/4 cols 2*(lane%4)+{0,1};
    // c2,c3 row+8.
    int g   = lane >> 2;
    int tig = lane & 3;
#pragma unroll
    for (int mi = 0; mi < 4; mi++) {
#pragma unroll
        for (int ni = 0; ni < 4; ni++) {
            int col = n0 + wn + ni * 8 + 2 * tig;
            float bx = 0.f, by = 0.f;
            if (bias) { bx = bias[col]; by = bias[col + 1]; }
            int r0 = m0 + wm + mi * 16 + g;
            float2 v0 = make_float2(acc[mi][ni][0] + bx, acc[mi][ni][1] + by);
            float2 v1 = make_float2(acc[mi][ni][2] + bx, acc[mi][ni][3] + by);
            *reinterpret_cast<float2*>(C + (size_t)r0 * N + col) = v0;
            *reinterpret_cast<float2*>(C + (size_t)(r0 + 8) * N + col) = v1;
        }
    }
}

// ============================================================================
// Launch
// ============================================================================
extern "C" void kernel_launch(void* const* d_in, const int* in_sizes, int n_in,
                              void* d_out, int out_size) {
    const float* x    = (const float*)d_in[0];
    const float* P0   = (const float*)d_in[1];
    const float* P1   = (const float*)d_in[2];
    const float* P2   = (const float*)d_in[3];
    const float* P3   = (const float*)d_in[4];
    const float* K0   = (const float*)d_in[5];
    const float* K1   = (const float*)d_in[6];
    const float* K2   = (const float*)d_in[7];
    const float* bias = (const float*)d_in[8];
    float* out = (float*)d_out;

    (void)in_sizes; (void)n_in; (void)out_size;

    // Idempotent, immediate-effect API (no stream op) -> legal during graph
    // capture; called unconditionally each time (no static guards allowed).
    cudaFuncSetAttribute(gemm_tn,
                         cudaFuncAttributeMaxDynamicSharedMemorySize,
                         GEMM_SMEM);

    float *S0t, *S1, *S2, *S3, *T0, *T1, *Mm;
    cudaGetSymbolAddress((void**)&S0t, g_S0t);
    cudaGetSymbolAddress((void**)&S1,  g_S1);
    cudaGetSymbolAddress((void**)&S2,  g_S2);
    cudaGetSymbolAddress((void**)&S3,  g_S3);
    cudaGetSymbolAddress((void**)&T0,  g_T0);
    cudaGetSymbolAddress((void**)&T1,  g_T1);
    cudaGetSymbolAddress((void**)&Mm,  g_M);

    // 1) Softmaxes. S0 written transposed (G0 = S0^T).
    softmax_kernel<<<DDIM, 256>>>(P0, S0t, 1);
    softmax_kernel<<<DDIM, 256>>>(P1, S1, 0);
    softmax_kernel<<<DDIM, 256>>>(P2, S2, 0);
    softmax_kernel<<<DDIM, 256>>>(P3, S3, 0);

    dim3 bdGrid(32, DDIM / 8), bdBlk(32, 8);
    dim3 gSmall(DDIM / 128, DDIM / 128);

    // 2) Compose W^T = S0^T·Bd0·S1^T·Bd1·S2^T·Bd2·S3^T, kept transposed so all
    //    dense products are the same TN GEMM:
    blockdiag_right<<<bdGrid, bdBlk>>>(S0t, K0, T0);                 // G1 = S0^T·Bd0
    gemm_tn<<<gSmall, 256, GEMM_SMEM>>>(T0, S1, T1, DDIM, DDIM, DDIM, nullptr); // G2 = G1·S1^T
    blockdiag_right<<<bdGrid, bdBlk>>>(T1, K1, T0);                  // G3 = G2·Bd1
    gemm_tn<<<gSmall, 256, GEMM_SMEM>>>(T0, S2, T1, DDIM, DDIM, DDIM, nullptr); // G4 = G3·S2^T
    blockdiag_right<<<bdGrid, bdBlk>>>(T1, K2, T0);                  // G5 = G4·Bd2
    gemm_tn<<<gSmall, 256, GEMM_SMEM>>>(S3, T0, Mm, DDIM, DDIM, DDIM, nullptr); // M[u][d]

    // 3) out[b][u] = sum_d x[b][d]·M[u][d] + bias[u]
    dim3 gBig(DDIM / 128, BDIM / 128);
    gemm_tn<<<gBig, 256, GEMM_SMEM>>>(x, Mm, out, BDIM, DDIM, DDIM, bias);
}